// round 11
// baseline (speedup 1.0000x reference)
#include <cuda_runtime.h>
#include <cstdint>

#define Bz    4
#define Cc    64
#define Hh    64
#define Ww    64
#define HW    4096
#define CHW   (Cc*HW)
#define PATCH 9
#define CHUNK 16
#define NCH   (Cc/CHUNK)            // 4
#define XW    32                    // x extent per CTA
#define NROWS 9                     // f2 window rows (dy = row)
#define SROW  40                    // 4 | 32 | 4 (floats)
#define F2BUF (CHUNK*NROWS*SROW)    // 5760 floats
#define F1BUF (CHUNK*XW)            // 512 floats
#define SMEM_FLOATS (2*(F2BUF+F1BUF))  // 12544
#define SMEM_BYTES  (SMEM_FLOATS*4)    // 50176
#define NTHR  288                   // 9 warps (warp = dy)
#define NARRIVE 160                 // 144 f2-row + 16 f1 copiers
#define CSTRIDE 36                  // combine scratch stride (conflict-free)

typedef unsigned long long u64;

// scratch
__device__ float g_inv1[Bz][HW];
__device__ float g_inv2p[Bz][72][72];   // padded inverse norms of f2 (halo = 1.0)

__device__ __forceinline__ uint32_t smem_u32(const void* p) {
    uint32_t a;
    asm("{ .reg .u64 t; cvta.to.shared.u64 t, %1; cvt.u32.u64 %0, t; }" : "=r"(a) : "l"(p));
    return a;
}
__device__ __forceinline__ void bulk_g2s(uint32_t dst, const float* src, uint32_t bytes,
                                         uint32_t mbar) {
    asm volatile("cp.async.bulk.shared::cta.global.mbarrier::complete_tx::bytes "
                 "[%0], [%1], %2, [%3];"
                 :: "r"(dst), "l"(src), "r"(bytes), "r"(mbar) : "memory");
}
__device__ __forceinline__ void mbar_init(uint32_t mbar, uint32_t cnt) {
    asm volatile("mbarrier.init.shared.b64 [%0], %1;" :: "r"(mbar), "r"(cnt) : "memory");
}
__device__ __forceinline__ void mbar_arrive_tx(uint32_t mbar, uint32_t tx) {
    asm volatile("mbarrier.arrive.expect_tx.shared.b64 _, [%0], %1;"
                 :: "r"(mbar), "r"(tx) : "memory");
}
__device__ __forceinline__ void mbar_arrive(uint32_t mbar) {
    asm volatile("mbarrier.arrive.shared.b64 _, [%0];" :: "r"(mbar) : "memory");
}
__device__ __forceinline__ void mbar_wait(uint32_t mbar, uint32_t parity) {
    uint32_t done;
    asm volatile("{\n\t.reg .pred p;\n\t"
                 "mbarrier.try_wait.parity.acquire.cta.shared::cta.b64 p, [%1], %2;\n\t"
                 "selp.b32 %0, 1, 0, p;\n\t}"
                 : "=r"(done) : "r"(mbar), "r"(parity) : "memory");
    if (!done) {
        asm volatile("{\n\t.reg .pred P1;\n\t"
                     "WL_%=:\n\t"
                     "mbarrier.try_wait.parity.acquire.cta.shared::cta.b64 P1, [%0], %1, 0x989680;\n\t"
                     "@P1 bra.uni WD_%=;\n\t"
                     "bra.uni WL_%=;\n\t"
                     "WD_%=:\n\t}"
                     :: "r"(mbar), "r"(parity) : "memory");
    }
}
__device__ __forceinline__ u64 pk(float lo, float hi) {
    u64 r; asm("mov.b64 %0, {%1, %2};" : "=l"(r) : "f"(lo), "f"(hi)); return r;
}
__device__ __forceinline__ void fma2(u64& d, u64 a, u64 b) {
    asm("fma.rn.f32x2 %0, %1, %2, %0;" : "+l"(d) : "l"(a), "l"(b));
}
__device__ __forceinline__ void unpk(u64 p, float& lo, float& hi) {
    asm("mov.b64 {%0, %1}, %2;" : "=f"(lo), "=f"(hi) : "l"(p));
}

// ---------------------------------------------------------------------------
// Kernel 1: inverse L2 norms. 65536 threads (256 CTAs), 8-way channel groups,
// MLP=8 per thread, 3-level shfl reduce. Also writes padded inv2 map + halo.
// ---------------------------------------------------------------------------
__global__ void invnorm_kernel(const float* __restrict__ f1,
                               const float* __restrict__ f2) {
    int idx  = blockIdx.x * 256 + threadIdx.x;          // 0..65535
    int cg   = idx & 7;                                 // 8 channel groups
    int quad = (idx >> 3) & 1023;
    int b    = (idx >> 13) & 3;
    int feat = idx >> 15;
    const float* src = (feat ? f2 : f1) + b * CHW + quad * 4 + cg * 8 * HW;

    float4 s = make_float4(0.f, 0.f, 0.f, 0.f);
#pragma unroll
    for (int i = 0; i < 8; ++i) {
        float4 v = __ldg((const float4*)(src + i * HW));
        s.x += v.x * v.x; s.y += v.y * v.y; s.z += v.z * v.z; s.w += v.w * v.w;
    }
#pragma unroll
    for (int m = 1; m <= 4; m <<= 1) {
        s.x += __shfl_xor_sync(0xffffffffu, s.x, m);
        s.y += __shfl_xor_sync(0xffffffffu, s.y, m);
        s.z += __shfl_xor_sync(0xffffffffu, s.z, m);
        s.w += __shfl_xor_sync(0xffffffffu, s.w, m);
    }
    if (cg == 0) {
        float4 r;
        r.x = rsqrtf(s.x + 1e-6f); r.y = rsqrtf(s.y + 1e-6f);
        r.z = rsqrtf(s.z + 1e-6f); r.w = rsqrtf(s.w + 1e-6f);
        int y = quad >> 4, x = (quad & 15) << 2;
        if (feat == 0) *(float4*)&g_inv1[b][quad * 4] = r;
        else           *(float4*)&g_inv2p[b][y + 4][x + 4] = r;
    }
    // halo of padded inv2 map (value irrelevant: raw sums there are 0)
    if (idx < Bz * 72 * 72) {
        int bb = idx / 5184;
        int rc = idx - bb * 5184;
        int r  = rc / 72, cc = rc - r * 72;
        if (r < 4 || r >= 68 || cc < 4 || cc >= 68)
            g_inv2p[bb][r][cc] = 1.0f;
    }
}

// ---------------------------------------------------------------------------
// Kernel 2: correlation + relu.
//   grid = [b:4][y:64][xhalf:2] = 512 CTAs, 288 threads (9 warps = 9 dy).
//   lane = (ch:2)(xq:3): 4 px, quarter of channels, all 9 dx.
//   Raw f2/f1 staged via double-buffered cp.async.bulk; LDS.128-only inner
//   loop (conflict-free phases); channel quarters combined via smem;
//   epilogue applies inv1*inv2p + relu.
// ---------------------------------------------------------------------------
__global__ __launch_bounds__(NTHR, 3)
void corr_kernel(const float* __restrict__ f1,
                 const float* __restrict__ f2,
                 float* __restrict__ out) {
    extern __shared__ float smem[];
    __shared__ u64 s_mbar[2];

    float* s_f2 = smem;                 // [2][CHUNK][NROWS][SROW]
    float* s_f1 = smem + 2 * F2BUF;     // [2][CHUNK][XW]
    const uint32_t s2 = smem_u32(s_f2);
    const uint32_t s1 = smem_u32(s_f1);
    const uint32_t mb0 = smem_u32(&s_mbar[0]);
    const uint32_t mb1 = smem_u32(&s_mbar[1]);

    const int b    = blockIdx.x >> 7;
    const int y    = (blockIdx.x >> 1) & 63;
    const int h    = blockIdx.x & 1;
    const int xb   = h * XW;
    const int tid  = threadIdx.x;
    const int dy   = tid >> 5;                 // warp = dy
    const int lane = tid & 31;
    const int ch   = lane >> 3;                // channel quarter (0..3)
    const int xq   = lane & 7;
    const int x0   = xq << 2;
    const int xg   = xb + x0;

    const float* f2b = f2 + b * CHW;
    const float* f1b = f1 + b * CHW;

    const int scol = h ? (xb - 4) : 0;         // global start col of f2 copy
    const int dcol = h ? 0 : 4;                // smem start col of f2 copy

    // copier indices (chunk-invariant)
    const int cs = tid / NROWS;                // f2 copier channel
    const int rs = tid - cs * NROWS;           // f2 copier row
    const int c1 = tid - CHUNK * NROWS;        // f1 copier channel
    const int rowg = y + rs - 4;
    const bool rvalid = (rowg >= 0) && (rowg < Hh);

    if (tid == 0) { mbar_init(mb0, NARRIVE); mbar_init(mb1, NARRIVE); }

    // one-time zeros: halo col + OOB-row interiors, both buffers (288 items)
    {
        int i   = tid;                         // exactly NTHR items
        int buf = i >= CHUNK * NROWS;
        int cr  = i - buf * CHUNK * NROWS;
        int c   = cr / NROWS, r = cr - c * NROWS;
        float* rowp = &s_f2[buf * F2BUF + (c * NROWS + r) * SROW];
        *(float4*)&rowp[h ? 36 : 0] = make_float4(0.f, 0.f, 0.f, 0.f);
        int row = y + r - 4;
        if (row < 0 || row >= Hh) {
            float4 z = make_float4(0.f, 0.f, 0.f, 0.f);
#pragma unroll
            for (int q = 0; q < 9; ++q) *(float4*)&rowp[dcol + q * 4] = z;
        }
        // mirror into the other buffer
        float* rowp2 = &s_f2[(1 - buf) * F2BUF + (c * NROWS + r) * SROW];
        *(float4*)&rowp2[h ? 36 : 0] = make_float4(0.f, 0.f, 0.f, 0.f);
        if (row < 0 || row >= Hh) {
            float4 z = make_float4(0.f, 0.f, 0.f, 0.f);
#pragma unroll
            for (int q = 0; q < 9; ++q) *(float4*)&rowp2[dcol + q * 4] = z;
        }
    }
    __syncthreads();

    auto stage = [&](int c0, int sel) {
        uint32_t mb = sel ? mb1 : mb0;
        if (tid < CHUNK * NROWS) {             // 144 f2-row copiers, 144B
            if (rvalid) {
                mbar_arrive_tx(mb, 144);
                bulk_g2s(s2 + (uint32_t)((sel * F2BUF + (cs * NROWS + rs) * SROW + dcol) * 4),
                         f2b + (c0 + cs) * HW + rowg * Ww + scol, 144, mb);
            } else {
                mbar_arrive(mb);
            }
        } else if (tid < NARRIVE) {            // 16 f1 copiers, 128B
            mbar_arrive_tx(mb, XW * 4);
            bulk_g2s(s1 + (uint32_t)((sel * F1BUF + c1 * XW) * 4),
                     f1b + (c0 + c1) * HW + y * Ww + xb, XW * 4, mb);
        }
    };

    u64 accE[5][2], accO[4][2];
#pragma unroll
    for (int e = 0; e < 5; ++e) { accE[e][0] = 0ull; accE[e][1] = 0ull; }
#pragma unroll
    for (int o = 0; o < 4; ++o) { accO[o][0] = 0ull; accO[o][1] = 0ull; }

    stage(0, 0);
    stage(CHUNK, 1);

#pragma unroll 1
    for (int k = 0; k < NCH; ++k) {
        mbar_wait(k & 1 ? mb1 : mb0, (k >> 1) & 1);

        const float* sbuf = s_f2 + (k & 1) * F2BUF + dy * SROW + x0;
        const float* abuf = s_f1 + (k & 1) * F1BUF + x0;
#pragma unroll
        for (int i = 0; i < CHUNK / 4; ++i) {
            const int c = (i << 2) + ch;
            const float* v = sbuf + c * (NROWS * SROW);
            float4 v0 = *(const float4*)(v);
            float4 v1 = *(const float4*)(v + 4);
            float4 v2 = *(const float4*)(v + 8);
            float4 af = *(const float4*)(abuf + c * XW);

            u64 w0 = pk(v0.x, v0.y), w1 = pk(v0.z, v0.w);
            u64 w2 = pk(v1.x, v1.y), w3 = pk(v1.z, v1.w);
            u64 w4 = pk(v2.x, v2.y), w5 = pk(v2.z, v2.w);
            u64 o0 = pk(v0.y, v0.z), o1 = pk(v0.w, v1.x);
            u64 o2 = pk(v1.y, v1.z), o3 = pk(v1.w, v2.x);
            u64 o4 = pk(v2.y, v2.z);
            u64 a01 = pk(af.x, af.y), a23 = pk(af.z, af.w);

            fma2(accE[0][0], a01, w0); fma2(accE[0][1], a23, w1);
            fma2(accE[1][0], a01, w1); fma2(accE[1][1], a23, w2);
            fma2(accE[2][0], a01, w2); fma2(accE[2][1], a23, w3);
            fma2(accE[3][0], a01, w3); fma2(accE[3][1], a23, w4);
            fma2(accE[4][0], a01, w4); fma2(accE[4][1], a23, w5);

            fma2(accO[0][0], a01, o0); fma2(accO[0][1], a23, o1);
            fma2(accO[1][0], a01, o1); fma2(accO[1][1], a23, o2);
            fma2(accO[2][0], a01, o2); fma2(accO[2][1], a23, o3);
            fma2(accO[3][0], a01, o3); fma2(accO[3][1], a23, o4);
        }
        if (k + 2 < NCH) {
            __syncthreads();
            stage((k + 2) * CHUNK, k & 1);
        }
    }

    // ---- unpack
    float r[PATCH][4];
#pragma unroll
    for (int e = 0; e < 5; ++e) {
        unpk(accE[e][0], r[2 * e][0], r[2 * e][1]);
        unpk(accE[e][1], r[2 * e][2], r[2 * e][3]);
    }
#pragma unroll
    for (int o = 0; o < 4; ++o) {
        unpk(accO[o][0], r[2 * o + 1][0], r[2 * o + 1][1]);
        unpk(accO[o][1], r[2 * o + 1][2], r[2 * o + 1][3]);
    }

    // ---- combine channel quarters via smem
    __syncthreads();
    const int pid = dy * 8 + xq;               // 0..71
    float* scr = smem;                          // [3][72][CSTRIDE]
    if (ch) {
        float* slot = scr + ((ch - 1) * 72 + pid) * CSTRIDE;
#pragma unroll
        for (int d = 0; d < PATCH; ++d)
            *(float4*)(slot + d * 4) = make_float4(r[d][0], r[d][1], r[d][2], r[d][3]);
    }
    __syncthreads();
    if (ch == 0) {
#pragma unroll
        for (int g = 0; g < 3; ++g) {
            const float* slot = scr + (g * 72 + pid) * CSTRIDE;
#pragma unroll
            for (int d = 0; d < PATCH; ++d) {
                float4 p = *(const float4*)(slot + d * 4);
                r[d][0] += p.x; r[d][1] += p.y; r[d][2] += p.z; r[d][3] += p.w;
            }
        }
        // epilogue: inv1 (this pixel) * inv2p (displaced pixel), relu, store
        float4 iv1 = *(const float4*)(&g_inv1[b][y * Ww + xg]);
        float e[12];
        *(float4*)&e[0] = *(const float4*)(&g_inv2p[b][y + dy][xg]);
        *(float4*)&e[4] = *(const float4*)(&g_inv2p[b][y + dy][xg + 4]);
        *(float4*)&e[8] = *(const float4*)(&g_inv2p[b][y + dy][xg + 8]);

        float* op = out + (size_t)(b * 81 + dy * PATCH) * HW + y * Ww + xg;
#pragma unroll
        for (int d = 0; d < PATCH; ++d) {
            float4 o;
            o.x = fmaxf(r[d][0] * iv1.x * e[d + 0], 0.f);
            o.y = fmaxf(r[d][1] * iv1.y * e[d + 1], 0.f);
            o.z = fmaxf(r[d][2] * iv1.z * e[d + 2], 0.f);
            o.w = fmaxf(r[d][3] * iv1.w * e[d + 3], 0.f);
            *(float4*)(op + d * HW) = o;
        }
    }
}

// ---------------------------------------------------------------------------
extern "C" void kernel_launch(void* const* d_in, const int* in_sizes, int n_in,
                              void* d_out, int out_size) {
    const float* f1 = (const float*)d_in[0];
    const float* f2 = (const float*)d_in[1];
    float* out = (float*)d_out;

    cudaFuncSetAttribute(corr_kernel,
                         cudaFuncAttributeMaxDynamicSharedMemorySize, SMEM_BYTES);

    invnorm_kernel<<<256, 256>>>(f1, f2);
    corr_kernel<<<Bz * Hh * 2, NTHR, SMEM_BYTES>>>(f1, f2, out);
}

// round 12
// speedup vs baseline: 1.3183x; 1.3183x over previous
#include <cuda_runtime.h>
#include <cstdint>

#define Bz    4
#define Cc    64
#define Hh    64
#define Ww    64
#define HW    4096
#define CHW   (Cc*HW)
#define PATCH 9
#define CHUNK 16
#define NCH   (Cc/CHUNK)            // 4
#define TY    2                     // rows per CTA
#define XW    32                    // x extent per CTA
#define SROW  40                    // 4 | 32 | 4
#define SROWS (TY+8)                // 10
#define F2BUF (CHUNK*SROWS*SROW)    // 6400 floats
#define F1BUF (CHUNK*TY*XW)         // 1024 floats
#define SMEM_FLOATS (2*(F2BUF+F1BUF))  // 14848
#define SMEM_BYTES  (SMEM_FLOATS*4)    // 59392
#define NTHR  288                   // 9 warps (warp = dy)
#define NARRIVE (CHUNK*SROWS + CHUNK*TY)  // 192

typedef unsigned long long u64;
union f4u { float4 f; ulonglong2 u; };

// scratch
__device__ float g_inv1[Bz][HW];
__device__ float g_inv2p[Bz][72][72];   // padded inverse norms of f2 (halo = 1.0)

__device__ __forceinline__ uint32_t smem_u32(const void* p) {
    uint32_t a;
    asm("{ .reg .u64 t; cvta.to.shared.u64 t, %1; cvt.u32.u64 %0, t; }" : "=r"(a) : "l"(p));
    return a;
}
__device__ __forceinline__ void bulk_g2s(uint32_t dst, const float* src, uint32_t bytes,
                                         uint32_t mbar) {
    asm volatile("cp.async.bulk.shared::cta.global.mbarrier::complete_tx::bytes "
                 "[%0], [%1], %2, [%3];"
                 :: "r"(dst), "l"(src), "r"(bytes), "r"(mbar) : "memory");
}
__device__ __forceinline__ void mbar_init(uint32_t mbar, uint32_t cnt) {
    asm volatile("mbarrier.init.shared.b64 [%0], %1;" :: "r"(mbar), "r"(cnt) : "memory");
}
__device__ __forceinline__ void mbar_arrive_tx(uint32_t mbar, uint32_t tx) {
    asm volatile("mbarrier.arrive.expect_tx.shared.b64 _, [%0], %1;"
                 :: "r"(mbar), "r"(tx) : "memory");
}
__device__ __forceinline__ void mbar_arrive(uint32_t mbar) {
    asm volatile("mbarrier.arrive.shared.b64 _, [%0];" :: "r"(mbar) : "memory");
}
__device__ __forceinline__ void mbar_wait(uint32_t mbar, uint32_t parity) {
    uint32_t done;
    asm volatile("{\n\t.reg .pred p;\n\t"
                 "mbarrier.try_wait.parity.acquire.cta.shared::cta.b64 p, [%1], %2;\n\t"
                 "selp.b32 %0, 1, 0, p;\n\t}"
                 : "=r"(done) : "r"(mbar), "r"(parity) : "memory");
    if (!done) {
        asm volatile("{\n\t.reg .pred P1;\n\t"
                     "WL_%=:\n\t"
                     "mbarrier.try_wait.parity.acquire.cta.shared::cta.b64 P1, [%0], %1, 0x989680;\n\t"
                     "@P1 bra.uni WD_%=;\n\t"
                     "bra.uni WL_%=;\n\t"
                     "WD_%=:\n\t}"
                     :: "r"(mbar), "r"(parity) : "memory");
    }
}
__device__ __forceinline__ u64 pk(float lo, float hi) {
    u64 r; asm("mov.b64 %0, {%1, %2};" : "=l"(r) : "f"(lo), "f"(hi)); return r;
}
__device__ __forceinline__ void fma2(u64& d, u64 a, u64 b) {
    asm("fma.rn.f32x2 %0, %1, %2, %0;" : "+l"(d) : "l"(a), "l"(b));
}
__device__ __forceinline__ void unpk(u64 p, float& lo, float& hi) {
    asm("mov.b64 {%0, %1}, %2;" : "=f"(lo), "=f"(hi) : "l"(p));
}

// ---------------------------------------------------------------------------
// Kernel 1: inverse L2 norms. 65536 threads (256 CTAs), 8-way channel groups,
// MLP=8 per thread, 3-level shfl reduce. Writes flat inv1 + padded inv2 map.
// ---------------------------------------------------------------------------
__global__ void invnorm_kernel(const float* __restrict__ f1,
                               const float* __restrict__ f2) {
    int idx  = blockIdx.x * 256 + threadIdx.x;          // 0..65535
    int cg   = idx & 7;
    int quad = (idx >> 3) & 1023;
    int b    = (idx >> 13) & 3;
    int feat = idx >> 15;
    const float* src = (feat ? f2 : f1) + b * CHW + quad * 4 + cg * 8 * HW;

    float4 s = make_float4(0.f, 0.f, 0.f, 0.f);
#pragma unroll
    for (int i = 0; i < 8; ++i) {
        float4 v = __ldg((const float4*)(src + i * HW));
        s.x += v.x * v.x; s.y += v.y * v.y; s.z += v.z * v.z; s.w += v.w * v.w;
    }
#pragma unroll
    for (int m = 1; m <= 4; m <<= 1) {
        s.x += __shfl_xor_sync(0xffffffffu, s.x, m);
        s.y += __shfl_xor_sync(0xffffffffu, s.y, m);
        s.z += __shfl_xor_sync(0xffffffffu, s.z, m);
        s.w += __shfl_xor_sync(0xffffffffu, s.w, m);
    }
    if (cg == 0) {
        float4 r;
        r.x = rsqrtf(s.x + 1e-6f); r.y = rsqrtf(s.y + 1e-6f);
        r.z = rsqrtf(s.z + 1e-6f); r.w = rsqrtf(s.w + 1e-6f);
        int y = quad >> 4, x = (quad & 15) << 2;
        if (feat == 0) *(float4*)&g_inv1[b][quad * 4] = r;
        else           *(float4*)&g_inv2p[b][y + 4][x + 4] = r;
    }
    if (idx < Bz * 72 * 72) {
        int bb = idx / 5184;
        int rc = idx - bb * 5184;
        int r  = rc / 72, cc = rc - r * 72;
        if (r < 4 || r >= 68 || cc < 4 || cc >= 68)
            g_inv2p[bb][r][cc] = 1.0f;
    }
}

// ---------------------------------------------------------------------------
// Kernel 2: correlation + relu (R8 skeleton, 27-slot inner loop).
//   grid = [b:4][ypair:32][xhalf:2] = 256 CTAs, 288 threads (9 warps).
//   warp = dy; lane = (ch:1)(ty:1)(xq:3) -> 4 px, half the channels.
//   Channel halves combined in-warp via float shfl_xor(16).
// ---------------------------------------------------------------------------
__global__ __launch_bounds__(NTHR, 2)
void corr_kernel(const float* __restrict__ f1,
                 const float* __restrict__ f2,
                 float* __restrict__ out) {
    extern __shared__ float smem[];
    __shared__ u64 s_mbar[2];

    float* s_f2 = smem;
    float* s_f1 = smem + 2 * F2BUF;
    const uint32_t s2 = smem_u32(s_f2);
    const uint32_t s1 = smem_u32(s_f1);
    const uint32_t mb0 = smem_u32(&s_mbar[0]);
    const uint32_t mb1 = smem_u32(&s_mbar[1]);

    const int b    = blockIdx.x >> 6;
    const int y0   = ((blockIdx.x >> 1) & 31) * TY;
    const int h    = blockIdx.x & 1;             // x half
    const int xb   = h * XW;
    const int tid  = threadIdx.x;
    const int dy   = tid >> 5;                   // warp = dy (0..8)
    const int lane = tid & 31;
    const int ch   = lane >> 4;                  // channel parity
    const int ty   = (lane >> 3) & 1;            // row in pair
    const int xq   = lane & 7;                   // x quad
    const int x0l  = xq << 2;
    const int y    = y0 + ty;
    const int xg   = xb + x0l;

    const float* f2b = f2 + b * CHW;
    const float* f1b = f1 + b * CHW;

    const int scol = h ? (xb - 4) : 0;
    const int dcol = h ? 0 : 4;

    if (tid == 0) { mbar_init(mb0, NARRIVE); mbar_init(mb1, NARRIVE); }

    // one-time zeros: x-halo side + interiors of OOB rows, both buffers
    for (int i = tid; i < 2 * CHUNK * SROWS; i += NTHR) {
        int buf = i >= CHUNK * SROWS;
        int cr  = i - buf * CHUNK * SROWS;
        int c   = cr / SROWS, r = cr - c * SROWS;
        float* rowp = &s_f2[buf * F2BUF + (c * SROWS + r) * SROW];
        *(float4*)&rowp[h ? 36 : 0] = make_float4(0.f, 0.f, 0.f, 0.f);
        int row = y0 + r - 4;
        if (row < 0 || row >= Hh) {
            float4 z = make_float4(0.f, 0.f, 0.f, 0.f);
#pragma unroll
            for (int q = 0; q < 9; ++q) *(float4*)&rowp[dcol + q * 4] = z;
        }
    }
    __syncthreads();

    auto stage = [&](int c0, int sel) {
        uint32_t mb = sel ? mb1 : mb0;
        if (tid < CHUNK * SROWS) {                   // 160 f2-row copiers, 144B
            int c = tid / SROWS, r = tid - c * SROWS;
            int row = y0 + r - 4;
            if (row >= 0 && row < Hh) {
                mbar_arrive_tx(mb, 144);
                bulk_g2s(s2 + (uint32_t)((sel * F2BUF + (c * SROWS + r) * SROW + dcol) * 4),
                         f2b + (c0 + c) * HW + row * Ww + scol, 144, mb);
            } else {
                mbar_arrive(mb);
            }
        } else if (tid < NARRIVE) {                  // 32 f1 copiers, 128B
            int i = tid - CHUNK * SROWS;
            int c = i >> 1, r = i & 1;
            mbar_arrive_tx(mb, XW * 4);
            bulk_g2s(s1 + (uint32_t)((sel * F1BUF + c * (TY * XW) + r * XW) * 4),
                     f1b + (c0 + c) * HW + (y0 + r) * Ww + xb, XW * 4, mb);
        }
    };

    // accumulators: even dx=2e as (px0,px1)/(px2,px3) pairs; odd dx=2o+1 as
    // (px1,px2) pair + px0/px3 scalars.
    u64 eacc[5][2];
    u64 macc[4];
    float s0a[4], s3a[4];
#pragma unroll
    for (int e = 0; e < 5; ++e) { eacc[e][0] = 0ull; eacc[e][1] = 0ull; }
#pragma unroll
    for (int o = 0; o < 4; ++o) { macc[o] = 0ull; s0a[o] = 0.f; s3a[o] = 0.f; }

    stage(0, 0);
    stage(CHUNK, 1);

#pragma unroll 1
    for (int k = 0; k < NCH; ++k) {
        mbar_wait(k & 1 ? mb1 : mb0, (k >> 1) & 1);

        const float* sbuf = s_f2 + (k & 1) * F2BUF + (dy + ty) * SROW + x0l;
        const float* abuf = s_f1 + (k & 1) * F1BUF + ty * XW + x0l;
#pragma unroll
        for (int i = 0; i < CHUNK / 2; ++i) {
            const int c = (i << 1) + ch;
            const float* s = sbuf + c * (SROWS * SROW);
            f4u v0, v1, v2, af;
            v0.f = *(const float4*)(s);
            v1.f = *(const float4*)(s + 4);
            v2.f = *(const float4*)(s + 8);
            af.f = *(const float4*)(abuf + c * (TY * XW));

            const u64 a01 = af.u.x;                 // (a0,a1) free
            const u64 a23 = af.u.y;                 // (a2,a3) free
            const u64 am  = pk(af.f.y, af.f.z);     // (a1,a2) — the ONE pack

            // even dx = 2e: pairs e and e+1 (all free u64 views)
            fma2(eacc[0][0], a01, v0.u.x); fma2(eacc[0][1], a23, v0.u.y);
            fma2(eacc[1][0], a01, v0.u.y); fma2(eacc[1][1], a23, v1.u.x);
            fma2(eacc[2][0], a01, v1.u.x); fma2(eacc[2][1], a23, v1.u.y);
            fma2(eacc[3][0], a01, v1.u.y); fma2(eacc[3][1], a23, v2.u.x);
            fma2(eacc[4][0], a01, v2.u.x); fma2(eacc[4][1], a23, v2.u.y);

            // odd dx = 2o+1: middle pair (px1,px2) + scalars px0/px3
            fma2(macc[0], am, v0.u.y);
            fma2(macc[1], am, v1.u.x);
            fma2(macc[2], am, v1.u.y);
            fma2(macc[3], am, v2.u.x);
            s0a[0] = fmaf(af.f.x, v0.f.y, s0a[0]);
            s0a[1] = fmaf(af.f.x, v0.f.w, s0a[1]);
            s0a[2] = fmaf(af.f.x, v1.f.y, s0a[2]);
            s0a[3] = fmaf(af.f.x, v1.f.w, s0a[3]);
            s3a[0] = fmaf(af.f.w, v1.f.x, s3a[0]);
            s3a[1] = fmaf(af.f.w, v1.f.z, s3a[1]);
            s3a[2] = fmaf(af.f.w, v2.f.x, s3a[2]);
            s3a[3] = fmaf(af.f.w, v2.f.z, s3a[3]);
        }
        if (k + 2 < NCH) {
            __syncthreads();
            stage((k + 2) * CHUNK, k & 1);
        }
    }

    // ---- assemble per-dx results
    float a[PATCH][4];
#pragma unroll
    for (int e = 0; e < 5; ++e) {
        unpk(eacc[e][0], a[2 * e][0], a[2 * e][1]);
        unpk(eacc[e][1], a[2 * e][2], a[2 * e][3]);
    }
#pragma unroll
    for (int o = 0; o < 4; ++o) {
        a[2 * o + 1][0] = s0a[o];
        unpk(macc[o], a[2 * o + 1][1], a[2 * o + 1][2]);
        a[2 * o + 1][3] = s3a[o];
    }

    // ---- combine channel halves in-warp (partner lane = xor 16)
#pragma unroll
    for (int d = 0; d < PATCH; ++d)
#pragma unroll
        for (int j = 0; j < 4; ++j)
            a[d][j] += __shfl_xor_sync(0xffffffffu, a[d][j], 16);

    if (ch == 0) {
        float4 iv1 = *(const float4*)(&g_inv1[b][y * Ww + xg]);
        float e[12];
        *(float4*)&e[0] = *(const float4*)(&g_inv2p[b][y + dy][xg]);
        *(float4*)&e[4] = *(const float4*)(&g_inv2p[b][y + dy][xg + 4]);
        *(float4*)&e[8] = *(const float4*)(&g_inv2p[b][y + dy][xg + 8]);

        float* op = out + (size_t)(b * 81 + dy * PATCH) * HW + y * Ww + xg;
#pragma unroll
        for (int d = 0; d < PATCH; ++d) {
            float4 o;
            o.x = fmaxf(a[d][0] * iv1.x * e[d + 0], 0.f);
            o.y = fmaxf(a[d][1] * iv1.y * e[d + 1], 0.f);
            o.z = fmaxf(a[d][2] * iv1.z * e[d + 2], 0.f);
            o.w = fmaxf(a[d][3] * iv1.w * e[d + 3], 0.f);
            *(float4*)(op + d * HW) = o;
        }
    }
}

// ---------------------------------------------------------------------------
extern "C" void kernel_launch(void* const* d_in, const int* in_sizes, int n_in,
                              void* d_out, int out_size) {
    const float* f1 = (const float*)d_in[0];
    const float* f2 = (const float*)d_in[1];
    float* out = (float*)d_out;

    cudaFuncSetAttribute(corr_kernel,
                         cudaFuncAttributeMaxDynamicSharedMemorySize, SMEM_BYTES);

    invnorm_kernel<<<256, 256>>>(f1, f2);
    corr_kernel<<<Bz * (Hh / TY) * 2, NTHR, SMEM_BYTES>>>(f1, f2, out);
}